// round 4
// baseline (speedup 1.0000x reference)
#include <cuda_runtime.h>
#include <cuda_bf16.h>

// DenseToSparse: x [B=32, C=64, H=128, W=128] f32 NCHW.
// Output: feats [B*H*W, C] = NHWC rows, active sites compacted to front
// (row-major site order), tail rows zero, count appended if room.
//
// SINGLE kernel: per-tile coalesced load -> flag -> block scan -> decoupled
// lookback -> scatter active rows AND zero this tile's share of the tail
// (tail chunk derived from the tile's own inactive prefix -- no global nnz
// needed). Last tile to finish its lookback resets all cross-call state so
// graph replays see identical initial conditions.

#define Bn 32
#define Cn 64
#define Hn 128
#define Wn 128
#define HWn (Hn * Wn)            // 16384
#define CHWn (Cn * HWn)          // 1048576
#define NSITES (Bn * HWn)        // 524288
#define NFEAT ((long long)NSITES * Cn)  // 33554432

#define TILE_SITES 128
#define NUM_TILES (NSITES / TILE_SITES) // 4096
#define THREADS 256
#define SSTRIDE 68               // words per site in smem; 68 % 32 == 4 ->
                                 // STS.128/LDS.128 bank-conflict-free

#define FLAG_A (1u << 30)
#define FLAG_P (2u << 30)
#define VAL_MASK 0x3FFFFFFFu

__device__ unsigned g_status[NUM_TILES];
__device__ unsigned g_tileCounter;
__device__ unsigned g_done;

__device__ __forceinline__ unsigned ldv(const unsigned* p) {
    return *(const volatile unsigned*)p;
}
__device__ __forceinline__ void stv(unsigned* p, unsigned v) {
    *(volatile unsigned*)p = v;
}

__global__ __launch_bounds__(THREADS) void d2s_kernel(
    const float* __restrict__ x, float* __restrict__ out, int write_count)
{
    __shared__ float vals[TILE_SITES * SSTRIDE];
    __shared__ unsigned rowOf[TILE_SITES];
    __shared__ unsigned char tflag[THREADS];
    __shared__ unsigned wsum[4];
    __shared__ unsigned s_tile, s_excl, s_agg, s_last;

    const int tid = threadIdx.x;
    const int lane = tid & 31;
    const int wid = tid >> 5;

    if (tid == 0) { s_tile = atomicAdd(&g_tileCounter, 1u); s_last = 0u; }
    __syncthreads();
    const unsigned tile = s_tile;

    // ---- load: 2 threads per site, 32 channels each, float4 smem staging ----
    const int half = tid >> 7;          // channel half: 0 -> c 0..31, 1 -> c 32..63
    const int sl = tid & 127;           // site within tile
    const int site = (int)tile * TILE_SITES + sl;
    const int b = site >> 14;           // site / HW
    const int s = site & (HWn - 1);     // site % HW
    const float* p = x + (long long)b * CHWn + (long long)(half * 32) * HWn + s;

    bool anyv = false;
#pragma unroll
    for (int c0 = 0; c0 < 32; c0 += 4) {
        float v0 = __ldg(p + (c0 + 0) * HWn);   // lanes -> consecutive addrs
        float v1 = __ldg(p + (c0 + 1) * HWn);
        float v2 = __ldg(p + (c0 + 2) * HWn);
        float v3 = __ldg(p + (c0 + 3) * HWn);
        anyv = anyv || (v0 != 0.0f) || (v1 != 0.0f) || (v2 != 0.0f) || (v3 != 0.0f);
        float4 pk = make_float4(v0, v1, v2, v3);
        *(float4*)&vals[sl * SSTRIDE + half * 32 + c0] = pk;  // STS.128, conflict-free
    }
    tflag[tid] = anyv ? 1 : 0;
    __syncthreads();

    // ---- per-site flag + block exclusive scan (threads 0..127) ----
    bool act = false;
    unsigned lanePref = 0;
    if (tid < TILE_SITES) {
        act = (tflag[tid] | tflag[tid + TILE_SITES]) != 0;
        unsigned ballot = __ballot_sync(0xffffffffu, act);
        lanePref = __popc(ballot & ((1u << lane) - 1u));
        if (lane == 0) wsum[wid] = __popc(ballot);
    }
    __syncthreads();

    // ---- decoupled lookback (warp 0; lane 0 also finalizes the block scan) ----
    if (wid == 0) {
        unsigned agg = 0;
        if (lane == 0) {
            unsigned acc = 0;
#pragma unroll
            for (int i = 0; i < 4; ++i) { unsigned t = wsum[i]; wsum[i] = acc; acc += t; }
            agg = acc;
            s_agg = acc;
        }
        if (tile == 0) {
            if (lane == 0) {
                stv(&g_status[0], FLAG_P | agg);
                s_excl = 0u;
            }
        } else {
            if (lane == 0) stv(&g_status[tile], FLAG_A | agg);
            unsigned excl = 0u;
            int t = (int)tile - 1;
            for (;;) {
                int idx = t - lane;
                unsigned st = (idx >= 0) ? ldv(&g_status[idx]) : FLAG_P;
                while (__any_sync(0xffffffffu, (st >> 30) == 0u)) {
                    if ((st >> 30) == 0u) st = ldv(&g_status[idx]);
                }
                unsigned pmask = __ballot_sync(0xffffffffu, (st >> 30) == 2u);
                if (pmask) {
                    int fp = __ffs(pmask) - 1;   // nearest tile with full prefix
                    unsigned contrib = (lane <= fp) ? (st & VAL_MASK) : 0u;
                    excl += __reduce_add_sync(0xffffffffu, contrib);
                    break;
                } else {
                    excl += __reduce_add_sync(0xffffffffu, st & VAL_MASK);
                    t -= 32;
                }
            }
            if (lane == 0) {
                s_excl = excl;
                stv(&g_status[tile], FLAG_P | (excl + agg));
                if (tile == NUM_TILES - 1 && write_count)
                    out[NFEAT] = (float)(excl + agg);
            }
        }
        // This tile will never read g_status again. Last tile to get here may
        // safely reset all cross-call state (no other reader can exist).
        if (lane == 0) {
            __threadfence();
            unsigned d = atomicAdd(&g_done, 1u);
            if (d == NUM_TILES - 1) s_last = 1u;
        }
    }
    __syncthreads();

    const unsigned excl = s_excl;
    const unsigned agg = s_agg;
    if (tid < TILE_SITES)
        rowOf[tid] = act ? (excl + wsum[wid] + lanePref) : 0xFFFFFFFFu;
    __syncthreads();

    float4* out4 = (float4*)out;

    // ---- vectorized scatter: 2048 float4 per tile, 8 per thread ----
#pragma unroll
    for (int k = 0; k < 8; ++k) {
        int f = k * THREADS + tid;
        int st = f >> 4;                 // site within tile
        int q = f & 15;                  // float4 within row
        unsigned r = rowOf[st];
        if (r != 0xFFFFFFFFu) {
            float4 v = *(const float4*)&vals[st * SSTRIDE + q * 4];  // LDS.128
            out4[(long long)r * 16 + q] = v;                          // 256B/warp runs
        }
    }

    // ---- zero this tile's share of the tail region ----
    // inactive exclusive prefix over site order: ie = 128*tile - excl
    // chunk: [NSITES - ie - inact, NSITES - ie)  -> disjoint, union = [nnz, NSITES)
    {
        unsigned inact = TILE_SITES - agg;
        long long zrow = (long long)NSITES - ((long long)tile * TILE_SITES - excl) - inact;
        int nq = (int)inact * 16;        // float4s to zero
        float4 z = make_float4(0.f, 0.f, 0.f, 0.f);
        for (int i = tid; i < nq; i += THREADS)
            out4[zrow * 16 + i] = z;
    }

    // ---- last-finishing tile resets lookback state for next invocation ----
    if (s_last) {
        for (int i = tid; i < NUM_TILES; i += THREADS) g_status[i] = 0u;
        if (tid == 0) { g_tileCounter = 0u; g_done = 0u; }
    }
}

extern "C" void kernel_launch(void* const* d_in, const int* in_sizes, int n_in,
                              void* d_out, int out_size) {
    const float* x = (const float*)d_in[0];
    float* out = (float*)d_out;
    int write_count = ((long long)out_size > NFEAT) ? 1 : 0;
    d2s_kernel<<<NUM_TILES, THREADS>>>(x, out, write_count);
}

// round 17
// speedup vs baseline: 1.0234x; 1.0234x over previous
#include <cuda_runtime.h>
#include <cuda_bf16.h>

// DenseToSparse: x [B=32, C=64, H=128, W=128] f32 NCHW.
// Output: feats [B*H*W, C] = NHWC rows, active sites compacted to front
// (row-major site order), tail rows zero, count appended if room.
//
// SINGLE kernel, decoupled lookback with a 128-wide window (4 statuses per
// lane per poll) and 256-site tiles: the serial prefix chain shrinks 8x vs
// the 32-wide/128-site version that measured issue=8.7%, DRAM=20%.
// Each tile also zeroes its own share of the tail region (derived from its
// inactive prefix), and the last tile resets all cross-call state.

#define Bn 32
#define Cn 64
#define Hn 128
#define Wn 128
#define HWn (Hn * Wn)            // 16384
#define CHWn (Cn * HWn)          // 1048576
#define NSITES (Bn * HWn)        // 524288
#define NFEAT ((long long)NSITES * Cn)  // 33554432

#define TILE_SITES 256
#define NUM_TILES (NSITES / TILE_SITES) // 2048
#define THREADS 512
#define SSTRIDE 68               // words per site in smem; 68 % 32 == 4 ->
                                 // STS.128/LDS.128 bank-conflict-free
#define VALS_BYTES (TILE_SITES * SSTRIDE * 4)  // 69632 (dynamic smem)

#define FLAG_A (1u << 30)
#define FLAG_P (2u << 30)
#define VAL_MASK 0x3FFFFFFFu

__device__ unsigned g_status[NUM_TILES];
__device__ unsigned g_tileCounter;
__device__ unsigned g_done;

__device__ __forceinline__ unsigned ldv(const unsigned* p) {
    return *(const volatile unsigned*)p;
}
__device__ __forceinline__ void stv(unsigned* p, unsigned v) {
    *(volatile unsigned*)p = v;
}

__global__ __launch_bounds__(THREADS, 3) void d2s_kernel(
    const float* __restrict__ x, float* __restrict__ out, int write_count)
{
    extern __shared__ unsigned char smem_raw[];
    float* vals = (float*)smem_raw;                 // [TILE_SITES * SSTRIDE]
    __shared__ unsigned rowOf[TILE_SITES];
    __shared__ unsigned char tflag[THREADS];
    __shared__ unsigned wsum[8];
    __shared__ unsigned s_tile, s_excl, s_agg, s_last;

    const int tid = threadIdx.x;
    const int lane = tid & 31;
    const int wid = tid >> 5;

    if (tid == 0) { s_tile = atomicAdd(&g_tileCounter, 1u); s_last = 0u; }
    __syncthreads();
    const unsigned tile = s_tile;

    // ---- load: 2 threads per site, 32 channels each, float4 smem staging ----
    const int half = tid >> 8;          // 0 -> channels 0..31, 1 -> 32..63
    const int sl = tid & 255;           // site within tile
    const int site = (int)tile * TILE_SITES + sl;
    const int b = site >> 14;           // site / HW
    const int s = site & (HWn - 1);     // site % HW
    const float* p = x + (long long)b * CHWn + (long long)(half * 32) * HWn + s;

    bool anyv = false;
#pragma unroll
    for (int c0 = 0; c0 < 32; c0 += 4) {
        float v0 = __ldg(p + (c0 + 0) * HWn);   // lanes -> consecutive addrs
        float v1 = __ldg(p + (c0 + 1) * HWn);
        float v2 = __ldg(p + (c0 + 2) * HWn);
        float v3 = __ldg(p + (c0 + 3) * HWn);
        anyv = anyv || (v0 != 0.0f) || (v1 != 0.0f) || (v2 != 0.0f) || (v3 != 0.0f);
        float4 pk = make_float4(v0, v1, v2, v3);
        *(float4*)&vals[sl * SSTRIDE + half * 32 + c0] = pk;  // STS.128
    }
    tflag[tid] = anyv ? 1 : 0;
    __syncthreads();

    // ---- per-site flag + block exclusive scan (threads 0..255, warps 0..7) ----
    bool act = false;
    unsigned lanePref = 0;
    if (tid < TILE_SITES) {
        act = (tflag[tid] | tflag[tid + TILE_SITES]) != 0;
        unsigned ballot = __ballot_sync(0xffffffffu, act);
        lanePref = __popc(ballot & ((1u << lane) - 1u));
        if (lane == 0) wsum[wid] = __popc(ballot);
    }
    __syncthreads();

    // ---- decoupled lookback, 128-wide window (warp 0) ----
    if (wid == 0) {
        unsigned agg = 0;
        if (lane == 0) {
            unsigned acc = 0;
#pragma unroll
            for (int i = 0; i < 8; ++i) { unsigned t = wsum[i]; wsum[i] = acc; acc += t; }
            agg = acc;
            s_agg = acc;
        }
        if (tile == 0) {
            if (lane == 0) {
                stv(&g_status[0], FLAG_P | agg);
                s_excl = 0u;
            }
        } else {
            if (lane == 0) stv(&g_status[tile], FLAG_A | agg);
            unsigned excl = 0u;
            int t = (int)tile - 1;
            for (;;) {
                unsigned st[4];
                int idx[4];
#pragma unroll
                for (int k = 0; k < 4; ++k) {
                    idx[k] = t - lane - 32 * k;
                    st[k] = (idx[k] >= 0) ? ldv(&g_status[idx[k]]) : FLAG_P;
                }
                // spin until all 128 statuses in the window are valid
                for (;;) {
                    bool bad = false;
#pragma unroll
                    for (int k = 0; k < 4; ++k) {
                        if ((st[k] >> 30) == 0u) {
                            st[k] = ldv(&g_status[idx[k]]);
                            if ((st[k] >> 30) == 0u) bad = true;
                        }
                    }
                    if (!__any_sync(0xffffffffu, bad)) break;
                }
                // nearest P: smallest k, then smallest lane
                int kP = -1, fp = 0;
#pragma unroll
                for (int k = 0; k < 4; ++k) {
                    if (kP < 0) {
                        unsigned pm = __ballot_sync(0xffffffffu, (st[k] >> 30) == 2u);
                        if (pm) { kP = k; fp = __ffs(pm) - 1; }
                    }
                }
                unsigned contrib = 0;
                if (kP < 0) {                      // no P in 128 -> sum all, hop
#pragma unroll
                    for (int k = 0; k < 4; ++k) contrib += st[k] & VAL_MASK;
                    excl += __reduce_add_sync(0xffffffffu, contrib);
                    t -= 128;
                } else {
                    for (int k = 0; k < kP; ++k) contrib += st[k] & VAL_MASK;
                    contrib += (lane <= fp) ? (st[kP] & VAL_MASK) : 0u;
                    excl += __reduce_add_sync(0xffffffffu, contrib);
                    break;
                }
            }
            if (lane == 0) {
                s_excl = excl;
                stv(&g_status[tile], FLAG_P | (excl + agg));
                if (tile == NUM_TILES - 1 && write_count)
                    out[NFEAT] = (float)(excl + agg);
            }
        }
        // This tile never reads g_status again; last finisher may reset state.
        if (lane == 0) {
            __threadfence();
            unsigned d = atomicAdd(&g_done, 1u);
            if (d == NUM_TILES - 1) s_last = 1u;
        }
    }
    __syncthreads();

    const unsigned excl = s_excl;
    const unsigned agg = s_agg;
    if (tid < TILE_SITES)
        rowOf[tid] = act ? (excl + wsum[wid] + lanePref) : 0xFFFFFFFFu;
    __syncthreads();

    float4* out4 = (float4*)out;

    // ---- vectorized scatter: 4096 float4 per tile, 8 per thread ----
#pragma unroll
    for (int k = 0; k < 8; ++k) {
        int f = k * THREADS + tid;
        int st = f >> 4;                 // site within tile
        int q = f & 15;                  // float4 within row
        unsigned r = rowOf[st];
        if (r != 0xFFFFFFFFu) {
            float4 v = *(const float4*)&vals[st * SSTRIDE + q * 4];  // LDS.128
            out4[(long long)r * 16 + q] = v;                          // 256B runs
        }
    }

    // ---- zero this tile's share of the tail region ----
    // inactive exclusive prefix: ie = 256*tile - excl
    // chunk: [NSITES - ie - inact, NSITES - ie) -> disjoint, union = [nnz, NSITES)
    {
        unsigned inact = TILE_SITES - agg;
        long long zrow = (long long)NSITES - ((long long)tile * TILE_SITES - excl) - inact;
        int nq = (int)inact * 16;        // float4s to zero
        float4 z = make_float4(0.f, 0.f, 0.f, 0.f);
        for (int i = tid; i < nq; i += THREADS)
            out4[zrow * 16 + i] = z;
    }

    // ---- last-finishing tile resets lookback state for next invocation ----
    if (s_last) {
        for (int i = tid; i < NUM_TILES; i += THREADS) g_status[i] = 0u;
        if (tid == 0) { g_tileCounter = 0u; g_done = 0u; }
    }
}

extern "C" void kernel_launch(void* const* d_in, const int* in_sizes, int n_in,
                              void* d_out, int out_size) {
    const float* x = (const float*)d_in[0];
    float* out = (float*)d_out;
    int write_count = ((long long)out_size > NFEAT) ? 1 : 0;

    cudaFuncSetAttribute(d2s_kernel,
                         cudaFuncAttributeMaxDynamicSharedMemorySize, VALS_BYTES);
    d2s_kernel<<<NUM_TILES, THREADS, VALS_BYTES>>>(x, out, write_count);
}